// round 3
// baseline (speedup 1.0000x reference)
#include <cuda_runtime.h>
#include <math.h>

// Problem constants (fixed by the dataset)
#define BB 16
#define NN 4000
#define TT (BB*NN)
#define KK 64
#define GHALF 364            // (9^3 - 1) / 2 half-space k-vectors, NMAX=4
#define ALPHA_C 0.3f
#define KCUT2_C 1.0f
#define COULOMB_C 14.399645351950548
#define INV_SQRT_PI 0.5641895835477563f

// Scratch (device globals — no allocation allowed)
__device__ float g_recip[BB*9];       // 2*pi * inv(cell)^T rows: rec[j*3+d]
__device__ float g_coef[BB*GHALF];
__device__ float g_Sre[BB*GHALF];
__device__ float g_Sim[BB*GHALF];
__device__ float g_Ereal[BB];

// Half-space k-vector enumeration:
//  idx <324 : nz = idx/81+1, ny = (idx%81)/9-4, nx = idx%9-4   (nz in 1..4)
//  idx <360 : nz = 0, ny = (idx-324)/9+1, nx = (idx-324)%9-4   (ny in 1..4)
//  idx <364 : nz = 0, ny = 0, nx = idx-359                      (nx in 1..4)
__device__ __forceinline__ void decode_idx(int idx, int& nx, int& ny, int& nz) {
    if (idx < 324)      { nz = idx/81 + 1; int r = idx%81; ny = r/9 - 4; nx = r%9 - 4; }
    else if (idx < 360) { int j = idx-324; nz = 0; ny = j/9 + 1; nx = j%9 - 4; }
    else                { nz = 0; ny = 0; nx = idx - 359; }
}

// ---------------------------------------------------------------------------
// k0: per-batch recip matrix, volume, coef table; zero accumulators.
// ---------------------------------------------------------------------------
__global__ void k0_prep(const float* __restrict__ cell) {
    int b = blockIdx.x;
    __shared__ float rec[9];
    __shared__ float svol;
    if (threadIdx.x == 0) {
        const float* c = cell + b*9;     // row-major cell[i][j]
        float a00=c[0],a01=c[1],a02=c[2];
        float a10=c[3],a11=c[4],a12=c[5];
        float a20=c[6],a21=c[7],a22=c[8];
        float co00 = a11*a22 - a12*a21;
        float co01 = a12*a20 - a10*a22;
        float co02 = a10*a21 - a11*a20;
        float det = a00*co00 + a01*co01 + a02*co02;
        float id = 1.0f/det;
        float m00 = co00*id;
        float m01 = (a02*a21 - a01*a22)*id;
        float m02 = (a01*a12 - a02*a11)*id;
        float m10 = co01*id;
        float m11 = (a00*a22 - a02*a20)*id;
        float m12 = (a02*a10 - a00*a12)*id;
        float m20 = co02*id;
        float m21 = (a01*a20 - a00*a21)*id;
        float m22 = (a00*a11 - a01*a10)*id;
        const float twopi = 6.283185307179586f;
        // rec[j*3+d] = 2*pi * inv[d][j]   (so phase = sum_j n_j * (rec_row_j . pos))
        rec[0]=twopi*m00; rec[1]=twopi*m10; rec[2]=twopi*m20;
        rec[3]=twopi*m01; rec[4]=twopi*m11; rec[5]=twopi*m21;
        rec[6]=twopi*m02; rec[7]=twopi*m12; rec[8]=twopi*m22;
        #pragma unroll
        for (int i=0;i<9;i++) g_recip[b*9+i]=rec[i];
        svol = fabsf(det);
        g_Ereal[b] = 0.0f;
    }
    __syncthreads();
    int idx = threadIdx.x;
    if (idx < GHALF) {
        int nx,ny,nz; decode_idx(idx,nx,ny,nz);
        float fx=(float)nx, fy=(float)ny, fz=(float)nz;
        float kx = fx*rec[0] + fy*rec[3] + fz*rec[6];
        float ky = fx*rec[1] + fy*rec[4] + fz*rec[7];
        float kz = fx*rec[2] + fy*rec[5] + fz*rec[8];
        float k2 = kx*kx + ky*ky + kz*kz;
        float coef = 0.0f;
        if (k2 > 1e-10f && k2 <= KCUT2_C) {
            float a2 = ALPHA_C*ALPHA_C;
            coef = 4.0f*3.14159265358979f * expf(-k2/(4.0f*a2)) / k2 / (2.0f*svol);
        }
        g_coef[b*GHALF+idx] = coef;
        g_Sre[b*GHALF+idx]  = 0.0f;
        g_Sim[b*GHALF+idx]  = 0.0f;
    }
}

// ---------------------------------------------------------------------------
// k1: real-space pair sum. One warp per atom, lane covers k and k+32.
// Block = 256 threads = 8 atoms (8 divides 4000, so single batch per block).
// ---------------------------------------------------------------------------
__global__ void k1_real(const float* __restrict__ pos, const float* __restrict__ q,
                        const float* __restrict__ cell,
                        const int* __restrict__ nm, const int* __restrict__ shifts,
                        const int* __restrict__ nneigh, const int* __restrict__ bidx) {
    int warp = threadIdx.x >> 5;
    int lane = threadIdx.x & 31;
    int t = blockIdx.x*8 + warp;
    __shared__ float cb[9];
    __shared__ float esum;
    int b = bidx[blockIdx.x*8];
    if (threadIdx.x < 9) cb[threadIdx.x] = cell[b*9 + threadIdx.x];
    if (threadIdx.x == 0) esum = 0.0f;
    __syncthreads();

    float px = pos[3*t], py = pos[3*t+1], pz = pos[3*t+2];
    float qt = q[t];
    int nn = nneigh[t];
    float acc = 0.0f;
    #pragma unroll
    for (int k = lane; k < KK; k += 32) {
        int j = nm[(long)t*KK + k];
        bool valid = (j >= 0) && (k < nn);
        int jj = valid ? j : 0;
        const int* sp = shifts + ((long)t*KK + k)*3;
        float sx = (float)sp[0], sy = (float)sp[1], sz = (float)sp[2];
        float ox = sx*cb[0] + sy*cb[3] + sz*cb[6];
        float oy = sx*cb[1] + sy*cb[4] + sz*cb[7];
        float oz = sx*cb[2] + sy*cb[5] + sz*cb[8];
        float dx = pos[3*jj]   + ox - px;
        float dy = pos[3*jj+1] + oy - py;
        float dz = pos[3*jj+2] + oz - pz;
        float d2 = dx*dx + dy*dy + dz*dz;
        if (valid) {
            float d = sqrtf(d2);
            acc += qt * q[jj] * erfcf(ALPHA_C*d) / d;
        }
    }
    #pragma unroll
    for (int o = 16; o; o >>= 1) acc += __shfl_down_sync(0xffffffffu, acc, o);
    if (lane == 0) {
        float e = 0.5f*acc - ALPHA_C*INV_SQRT_PI*qt*qt;
        atomicAdd(&esum, e);
    }
    __syncthreads();
    if (threadIdx.x == 0) atomicAdd(&g_Ereal[b], esum);
}

// ---------------------------------------------------------------------------
// k2: reciprocal structure factors via separable phase factors.
// Block = 128 threads, processes CHUNK=128 atoms of one batch.
// Phase 1: each thread builds (px[9], py[9], pz_q[5]) for one atom.
// Phase 2: threads 0..80 own (nx,ny) and accumulate nz=1..4;
//          threads 81..120 own the 40 nz=0 half-plane vectors.
// ---------------------------------------------------------------------------
#define CHUNK 128
__global__ void k2_recip(const float* __restrict__ pos, const float* __restrict__ q) {
    __shared__ float2 PX[CHUNK][9];
    __shared__ float2 PY[CHUNK][9];
    __shared__ float2 PZ[CHUNK][5];   // q folded in: PZ[0]=(q,0), PZ[k]=q*e^{i k u2}
    int b   = blockIdx.y;
    int tid = threadIdx.x;
    int a   = blockIdx.x*CHUNK + tid;

    if (a < NN) {
        int t = b*NN + a;
        float x = pos[3*t], y = pos[3*t+1], z = pos[3*t+2];
        float qv = q[t];
        const float* R = g_recip + b*9;
        float u0 = R[0]*x + R[1]*y + R[2]*z;
        float u1 = R[3]*x + R[4]*y + R[5]*z;
        float u2 = R[6]*x + R[7]*y + R[8]*z;
        float s, c;
        // X axis
        sincosf(u0, &s, &c);
        {
            float2 e = make_float2(c, s);
            float2 p = make_float2(1.0f, 0.0f);
            PX[tid][4] = p;
            #pragma unroll
            for (int k = 1; k <= 4; k++) {
                float2 np = make_float2(p.x*e.x - p.y*e.y, p.x*e.y + p.y*e.x);
                p = np;
                PX[tid][4+k] = p;
                PX[tid][4-k] = make_float2(p.x, -p.y);
            }
        }
        // Y axis
        sincosf(u1, &s, &c);
        {
            float2 e = make_float2(c, s);
            float2 p = make_float2(1.0f, 0.0f);
            PY[tid][4] = p;
            #pragma unroll
            for (int k = 1; k <= 4; k++) {
                float2 np = make_float2(p.x*e.x - p.y*e.y, p.x*e.y + p.y*e.x);
                p = np;
                PY[tid][4+k] = p;
                PY[tid][4-k] = make_float2(p.x, -p.y);
            }
        }
        // Z axis (q folded)
        sincosf(u2, &s, &c);
        {
            float2 e = make_float2(c, s);
            float2 p = make_float2(qv, 0.0f);
            PZ[tid][0] = p;
            #pragma unroll
            for (int k = 1; k <= 4; k++) {
                float2 np = make_float2(p.x*e.x - p.y*e.y, p.x*e.y + p.y*e.x);
                p = np;
                PZ[tid][k] = p;
            }
        }
    } else {
        float2 zz = make_float2(0.0f, 0.0f);
        #pragma unroll
        for (int k = 0; k < 9; k++) { PX[tid][k] = zz; PY[tid][k] = zz; }
        #pragma unroll
        for (int k = 0; k < 5; k++) PZ[tid][k] = zz;
    }
    __syncthreads();

    bool is_main = (tid < 81);
    bool is_edge = (tid >= 81) && (tid < 121);
    int nxi = 0, nyi = 0;
    if (is_main)      { nxi = tid % 9;  nyi = tid / 9; }
    else if (is_edge) {
        int j = tid - 81;
        if (j < 36) { nyi = j/9 + 5; nxi = j%9; }          // ny=1..4, nx=-4..4
        else        { nyi = 4;       nxi = tid - 112; }     // ny=0,   nx=1..4
    }

    if (is_main) {
        float Sr0=0,Si0=0,Sr1=0,Si1=0,Sr2=0,Si2=0,Sr3=0,Si3=0;
        #pragma unroll 2
        for (int aa = 0; aa < CHUNK; aa++) {
            float2 fx = PX[aa][nxi];
            float2 fy = PY[aa][nyi];
            float tr = fx.x*fy.x - fx.y*fy.y;
            float ti = fx.x*fy.y + fx.y*fy.x;
            float2 z1 = PZ[aa][1], z2 = PZ[aa][2], z3 = PZ[aa][3], z4 = PZ[aa][4];
            Sr0 += tr*z1.x - ti*z1.y;  Si0 += tr*z1.y + ti*z1.x;
            Sr1 += tr*z2.x - ti*z2.y;  Si1 += tr*z2.y + ti*z2.x;
            Sr2 += tr*z3.x - ti*z3.y;  Si2 += tr*z3.y + ti*z3.x;
            Sr3 += tr*z4.x - ti*z4.y;  Si3 += tr*z4.y + ti*z4.x;
        }
        int base = b*GHALF + tid;
        atomicAdd(&g_Sre[base        ], Sr0); atomicAdd(&g_Sim[base        ], Si0);
        atomicAdd(&g_Sre[base +  81  ], Sr1); atomicAdd(&g_Sim[base +  81  ], Si1);
        atomicAdd(&g_Sre[base + 162  ], Sr2); atomicAdd(&g_Sim[base + 162  ], Si2);
        atomicAdd(&g_Sre[base + 243  ], Sr3); atomicAdd(&g_Sim[base + 243  ], Si3);
    } else if (is_edge) {
        float Sr = 0, Si = 0;
        #pragma unroll 2
        for (int aa = 0; aa < CHUNK; aa++) {
            float2 fx = PX[aa][nxi];
            float2 fy = PY[aa][nyi];
            float tr = fx.x*fy.x - fx.y*fy.y;
            float ti = fx.x*fy.y + fx.y*fy.x;
            float qz = PZ[aa][0].x;    // (q, 0)
            Sr += tr*qz;
            Si += ti*qz;
        }
        int idx = b*GHALF + 324 + (tid - 81);
        atomicAdd(&g_Sre[idx], Sr);
        atomicAdd(&g_Sim[idx], Si);
    }
}

// ---------------------------------------------------------------------------
// k3: per-batch final energy: E = (Ereal + 2 * sum_g coef*(Sre^2+Sim^2)) * C
// ---------------------------------------------------------------------------
__global__ void k3_final(float* __restrict__ out) {
    int b = blockIdx.x;
    float v = 0.0f;
    for (int i = threadIdx.x; i < GHALF; i += 128) {
        float sr = g_Sre[b*GHALF+i];
        float si = g_Sim[b*GHALF+i];
        v = fmaf(g_coef[b*GHALF+i], sr*sr + si*si, v);
    }
    #pragma unroll
    for (int o = 16; o; o >>= 1) v += __shfl_down_sync(0xffffffffu, v, o);
    __shared__ float red[4];
    int w = threadIdx.x >> 5, l = threadIdx.x & 31;
    if (l == 0) red[w] = v;
    __syncthreads();
    if (threadIdx.x == 0) {
        float tot = red[0] + red[1] + red[2] + red[3];
        out[b] = (float)(((double)g_Ereal[b] + 2.0*(double)tot) * COULOMB_C);
    }
}

// ---------------------------------------------------------------------------
extern "C" void kernel_launch(void* const* d_in, const int* in_sizes, int n_in,
                              void* d_out, int out_size) {
    const float* positions = (const float*)d_in[0];
    const float* charges   = (const float*)d_in[1];
    const float* cell      = (const float*)d_in[2];
    const int*   nm        = (const int*)d_in[3];
    const int*   shifts    = (const int*)d_in[4];
    const int*   nneigh    = (const int*)d_in[5];
    const int*   bidx      = (const int*)d_in[6];
    float* out = (float*)d_out;

    k0_prep<<<BB, 384>>>(cell);
    k1_real<<<TT/8, 256>>>(positions, charges, cell, nm, shifts, nneigh, bidx);
    dim3 g2((NN + CHUNK - 1)/CHUNK, BB);
    k2_recip<<<g2, CHUNK>>>(positions, charges);
    k3_final<<<BB, 128>>>(out);
}

// round 4
// speedup vs baseline: 1.0043x; 1.0043x over previous
#include <cuda_runtime.h>
#include <math.h>

// Problem constants (fixed by the dataset)
#define BB 16
#define NN 4000
#define TT (BB*NN)
#define KK 64
#define GHALF 364            // (9^3 - 1) / 2 half-space k-vectors, NMAX=4
#define ALPHA_C 0.3f
#define KCUT2_C 1.0f
#define COULOMB_C 14.399645351950548
#define INV_SQRT_PI 0.5641895835477563f

// Scratch (device globals — no allocation allowed)
__device__ float g_recip[BB*9];       // 2*pi * inv(cell)^T rows: rec[j*3+d]
__device__ float g_coef[BB*GHALF];
__device__ float g_Sre[BB*GHALF];
__device__ float g_Sim[BB*GHALF];
__device__ float g_Ereal[BB];

// Half-space k-vector enumeration:
//  idx <324 : nz = idx/81+1, ny = (idx%81)/9-4, nx = idx%9-4   (nz in 1..4)
//  idx <360 : nz = 0, ny = (idx-324)/9+1, nx = (idx-324)%9-4   (ny in 1..4)
//  idx <364 : nz = 0, ny = 0, nx = idx-359                      (nx in 1..4)
__device__ __forceinline__ void decode_idx(int idx, int& nx, int& ny, int& nz) {
    if (idx < 324)      { nz = idx/81 + 1; int r = idx%81; ny = r/9 - 4; nx = r%9 - 4; }
    else if (idx < 360) { int j = idx-324; nz = 0; ny = j/9 + 1; nx = j%9 - 4; }
    else                { nz = 0; ny = 0; nx = idx - 359; }
}

// ---------------------------------------------------------------------------
// k0: per-batch recip matrix, volume, coef table; zero accumulators.
// ---------------------------------------------------------------------------
__global__ void k0_prep(const float* __restrict__ cell) {
    int b = blockIdx.x;
    __shared__ float rec[9];
    __shared__ float svol;
    if (threadIdx.x == 0) {
        const float* c = cell + b*9;     // row-major cell[i][j]
        float a00=c[0],a01=c[1],a02=c[2];
        float a10=c[3],a11=c[4],a12=c[5];
        float a20=c[6],a21=c[7],a22=c[8];
        float co00 = a11*a22 - a12*a21;
        float co01 = a12*a20 - a10*a22;
        float co02 = a10*a21 - a11*a20;
        float det = a00*co00 + a01*co01 + a02*co02;
        float id = 1.0f/det;
        float m00 = co00*id;
        float m01 = (a02*a21 - a01*a22)*id;
        float m02 = (a01*a12 - a02*a11)*id;
        float m10 = co01*id;
        float m11 = (a00*a22 - a02*a20)*id;
        float m12 = (a02*a10 - a00*a12)*id;
        float m20 = co02*id;
        float m21 = (a01*a20 - a00*a21)*id;
        float m22 = (a00*a11 - a01*a10)*id;
        const float twopi = 6.283185307179586f;
        // rec[j*3+d] = 2*pi * inv[d][j]   (so phase = sum_j n_j * (rec_row_j . pos))
        rec[0]=twopi*m00; rec[1]=twopi*m10; rec[2]=twopi*m20;
        rec[3]=twopi*m01; rec[4]=twopi*m11; rec[5]=twopi*m21;
        rec[6]=twopi*m02; rec[7]=twopi*m12; rec[8]=twopi*m22;
        #pragma unroll
        for (int i=0;i<9;i++) g_recip[b*9+i]=rec[i];
        svol = fabsf(det);
        g_Ereal[b] = 0.0f;
    }
    __syncthreads();
    int idx = threadIdx.x;
    if (idx < GHALF) {
        int nx,ny,nz; decode_idx(idx,nx,ny,nz);
        float fx=(float)nx, fy=(float)ny, fz=(float)nz;
        float kx = fx*rec[0] + fy*rec[3] + fz*rec[6];
        float ky = fx*rec[1] + fy*rec[4] + fz*rec[7];
        float kz = fx*rec[2] + fy*rec[5] + fz*rec[8];
        float k2 = kx*kx + ky*ky + kz*kz;
        float coef = 0.0f;
        if (k2 > 1e-10f && k2 <= KCUT2_C) {
            float a2 = ALPHA_C*ALPHA_C;
            coef = 4.0f*3.14159265358979f * expf(-k2/(4.0f*a2)) / k2 / (2.0f*svol);
        }
        g_coef[b*GHALF+idx] = coef;
        g_Sre[b*GHALF+idx]  = 0.0f;
        g_Sim[b*GHALF+idx]  = 0.0f;
    }
}

// ---------------------------------------------------------------------------
// k1: real-space pair sum. One warp per atom, lane covers k and k+32.
// Block = 256 threads = 8 atoms (8 divides 4000, so single batch per block).
// ---------------------------------------------------------------------------
__global__ void k1_real(const float* __restrict__ pos, const float* __restrict__ q,
                        const float* __restrict__ cell,
                        const int* __restrict__ nm, const int* __restrict__ shifts,
                        const int* __restrict__ nneigh, const int* __restrict__ bidx) {
    int warp = threadIdx.x >> 5;
    int lane = threadIdx.x & 31;
    int t = blockIdx.x*8 + warp;
    __shared__ float cb[9];
    __shared__ float esum;
    int b = bidx[blockIdx.x*8];
    if (threadIdx.x < 9) cb[threadIdx.x] = cell[b*9 + threadIdx.x];
    if (threadIdx.x == 0) esum = 0.0f;
    __syncthreads();

    float px = pos[3*t], py = pos[3*t+1], pz = pos[3*t+2];
    float qt = q[t];
    int nn = nneigh[t];
    float acc = 0.0f;
    #pragma unroll
    for (int k = lane; k < KK; k += 32) {
        int j = nm[(long)t*KK + k];
        bool valid = (j >= 0) && (k < nn);
        int jj = valid ? j : 0;
        const int* sp = shifts + ((long)t*KK + k)*3;
        float sx = (float)sp[0], sy = (float)sp[1], sz = (float)sp[2];
        float ox = sx*cb[0] + sy*cb[3] + sz*cb[6];
        float oy = sx*cb[1] + sy*cb[4] + sz*cb[7];
        float oz = sx*cb[2] + sy*cb[5] + sz*cb[8];
        float dx = pos[3*jj]   + ox - px;
        float dy = pos[3*jj+1] + oy - py;
        float dz = pos[3*jj+2] + oz - pz;
        float d2 = dx*dx + dy*dy + dz*dz;
        if (valid) {
            float d = sqrtf(d2);
            acc += qt * q[jj] * erfcf(ALPHA_C*d) / d;
        }
    }
    #pragma unroll
    for (int o = 16; o; o >>= 1) acc += __shfl_down_sync(0xffffffffu, acc, o);
    if (lane == 0) {
        float e = 0.5f*acc - ALPHA_C*INV_SQRT_PI*qt*qt;
        atomicAdd(&esum, e);
    }
    __syncthreads();
    if (threadIdx.x == 0) atomicAdd(&g_Ereal[b], esum);
}

// ---------------------------------------------------------------------------
// k2: reciprocal structure factors via separable phase factors.
// Block = 128 threads, processes CHUNK=128 atoms of one batch.
// Phase 1: each thread builds (px[9], py[9], pz_q[5]) for one atom.
// Phase 2: threads 0..80 own (nx,ny) and accumulate nz=1..4;
//          threads 81..120 own the 40 nz=0 half-plane vectors.
// ---------------------------------------------------------------------------
#define CHUNK 128
__global__ void k2_recip(const float* __restrict__ pos, const float* __restrict__ q) {
    __shared__ float2 PX[CHUNK][9];
    __shared__ float2 PY[CHUNK][9];
    __shared__ float2 PZ[CHUNK][5];   // q folded in: PZ[0]=(q,0), PZ[k]=q*e^{i k u2}
    int b   = blockIdx.y;
    int tid = threadIdx.x;
    int a   = blockIdx.x*CHUNK + tid;

    if (a < NN) {
        int t = b*NN + a;
        float x = pos[3*t], y = pos[3*t+1], z = pos[3*t+2];
        float qv = q[t];
        const float* R = g_recip + b*9;
        float u0 = R[0]*x + R[1]*y + R[2]*z;
        float u1 = R[3]*x + R[4]*y + R[5]*z;
        float u2 = R[6]*x + R[7]*y + R[8]*z;
        float s, c;
        // X axis
        sincosf(u0, &s, &c);
        {
            float2 e = make_float2(c, s);
            float2 p = make_float2(1.0f, 0.0f);
            PX[tid][4] = p;
            #pragma unroll
            for (int k = 1; k <= 4; k++) {
                float2 np = make_float2(p.x*e.x - p.y*e.y, p.x*e.y + p.y*e.x);
                p = np;
                PX[tid][4+k] = p;
                PX[tid][4-k] = make_float2(p.x, -p.y);
            }
        }
        // Y axis
        sincosf(u1, &s, &c);
        {
            float2 e = make_float2(c, s);
            float2 p = make_float2(1.0f, 0.0f);
            PY[tid][4] = p;
            #pragma unroll
            for (int k = 1; k <= 4; k++) {
                float2 np = make_float2(p.x*e.x - p.y*e.y, p.x*e.y + p.y*e.x);
                p = np;
                PY[tid][4+k] = p;
                PY[tid][4-k] = make_float2(p.x, -p.y);
            }
        }
        // Z axis (q folded)
        sincosf(u2, &s, &c);
        {
            float2 e = make_float2(c, s);
            float2 p = make_float2(qv, 0.0f);
            PZ[tid][0] = p;
            #pragma unroll
            for (int k = 1; k <= 4; k++) {
                float2 np = make_float2(p.x*e.x - p.y*e.y, p.x*e.y + p.y*e.x);
                p = np;
                PZ[tid][k] = p;
            }
        }
    } else {
        float2 zz = make_float2(0.0f, 0.0f);
        #pragma unroll
        for (int k = 0; k < 9; k++) { PX[tid][k] = zz; PY[tid][k] = zz; }
        #pragma unroll
        for (int k = 0; k < 5; k++) PZ[tid][k] = zz;
    }
    __syncthreads();

    bool is_main = (tid < 81);
    bool is_edge = (tid >= 81) && (tid < 121);
    int nxi = 0, nyi = 0;
    if (is_main)      { nxi = tid % 9;  nyi = tid / 9; }
    else if (is_edge) {
        int j = tid - 81;
        if (j < 36) { nyi = j/9 + 5; nxi = j%9; }          // ny=1..4, nx=-4..4
        else        { nyi = 4;       nxi = tid - 112; }     // ny=0,   nx=1..4
    }

    if (is_main) {
        float Sr0=0,Si0=0,Sr1=0,Si1=0,Sr2=0,Si2=0,Sr3=0,Si3=0;
        #pragma unroll 2
        for (int aa = 0; aa < CHUNK; aa++) {
            float2 fx = PX[aa][nxi];
            float2 fy = PY[aa][nyi];
            float tr = fx.x*fy.x - fx.y*fy.y;
            float ti = fx.x*fy.y + fx.y*fy.x;
            float2 z1 = PZ[aa][1], z2 = PZ[aa][2], z3 = PZ[aa][3], z4 = PZ[aa][4];
            Sr0 += tr*z1.x - ti*z1.y;  Si0 += tr*z1.y + ti*z1.x;
            Sr1 += tr*z2.x - ti*z2.y;  Si1 += tr*z2.y + ti*z2.x;
            Sr2 += tr*z3.x - ti*z3.y;  Si2 += tr*z3.y + ti*z3.x;
            Sr3 += tr*z4.x - ti*z4.y;  Si3 += tr*z4.y + ti*z4.x;
        }
        int base = b*GHALF + tid;
        atomicAdd(&g_Sre[base        ], Sr0); atomicAdd(&g_Sim[base        ], Si0);
        atomicAdd(&g_Sre[base +  81  ], Sr1); atomicAdd(&g_Sim[base +  81  ], Si1);
        atomicAdd(&g_Sre[base + 162  ], Sr2); atomicAdd(&g_Sim[base + 162  ], Si2);
        atomicAdd(&g_Sre[base + 243  ], Sr3); atomicAdd(&g_Sim[base + 243  ], Si3);
    } else if (is_edge) {
        float Sr = 0, Si = 0;
        #pragma unroll 2
        for (int aa = 0; aa < CHUNK; aa++) {
            float2 fx = PX[aa][nxi];
            float2 fy = PY[aa][nyi];
            float tr = fx.x*fy.x - fx.y*fy.y;
            float ti = fx.x*fy.y + fx.y*fy.x;
            float qz = PZ[aa][0].x;    // (q, 0)
            Sr += tr*qz;
            Si += ti*qz;
        }
        int idx = b*GHALF + 324 + (tid - 81);
        atomicAdd(&g_Sre[idx], Sr);
        atomicAdd(&g_Sim[idx], Si);
    }
}

// ---------------------------------------------------------------------------
// k3: per-batch final energy: E = (Ereal + 2 * sum_g coef*(Sre^2+Sim^2)) * C
// ---------------------------------------------------------------------------
__global__ void k3_final(float* __restrict__ out) {
    int b = blockIdx.x;
    float v = 0.0f;
    for (int i = threadIdx.x; i < GHALF; i += 128) {
        float sr = g_Sre[b*GHALF+i];
        float si = g_Sim[b*GHALF+i];
        v = fmaf(g_coef[b*GHALF+i], sr*sr + si*si, v);
    }
    #pragma unroll
    for (int o = 16; o; o >>= 1) v += __shfl_down_sync(0xffffffffu, v, o);
    __shared__ float red[4];
    int w = threadIdx.x >> 5, l = threadIdx.x & 31;
    if (l == 0) red[w] = v;
    __syncthreads();
    if (threadIdx.x == 0) {
        float tot = red[0] + red[1] + red[2] + red[3];
        out[b] = (float)(((double)g_Ereal[b] + 2.0*(double)tot) * COULOMB_C);
    }
}

// ---------------------------------------------------------------------------
extern "C" void kernel_launch(void* const* d_in, const int* in_sizes, int n_in,
                              void* d_out, int out_size) {
    const float* positions = (const float*)d_in[0];
    const float* charges   = (const float*)d_in[1];
    const float* cell      = (const float*)d_in[2];
    const int*   nm        = (const int*)d_in[3];
    const int*   shifts    = (const int*)d_in[4];
    const int*   nneigh    = (const int*)d_in[5];
    const int*   bidx      = (const int*)d_in[6];
    float* out = (float*)d_out;

    k0_prep<<<BB, 384>>>(cell);
    k1_real<<<TT/8, 256>>>(positions, charges, cell, nm, shifts, nneigh, bidx);
    dim3 g2((NN + CHUNK - 1)/CHUNK, BB);
    k2_recip<<<g2, CHUNK>>>(positions, charges);
    k3_final<<<BB, 128>>>(out);
}